// round 15
// baseline (speedup 1.0000x reference)
#include <cuda_runtime.h>
#include <cuda_fp16.h>
#include <cstdint>

#define SQ 8192
#define DIMN 512
#define SCALE 0.04419417382415922f  // 1/sqrt(512)
#define KCHUNK 32                   // k per tile; 2 tiles per pipeline step
#define T2_STAGE_BYTES 32768u       // A0 8K | B0 8K | A1 8K | B1 8K
#define T2_NSTAGE 3                 // 96 KB total -> 2 CTAs/SM
#define KSEG 2048                   // AV split-K segment width

// fp16 operands (zero-initialized device globals)
__device__ __half g_x16[SQ * DIMN];                            // x single fp16
__device__ __half g_w16[3 * DIMN * DIMN];                      // Wq|Wk|Wv single fp16
__device__ __half g_q16[SQ * DIMN];
__device__ __half g_k16[SQ * DIMN];                            // pre-scaled by SCALE
__device__ __half g_vth[DIMN * SQ];                            // V^T: [512, 8192]
__device__ __half g_aw[(size_t)SQ * SQ];                       // raw scores -> weights
// split-K partials for AV: 256 tiles x 4 segs x 128x128 fp32 = 64 MB
__device__ float g_part[(size_t)256 * 4 * 16384];

// ---------------------------------------------------------------------------
// PTX helpers (base-ISA only: ldmatrix / mma.sync / cp.async)
// ---------------------------------------------------------------------------
__device__ __forceinline__ uint32_t smem_u32(const void* p) {
    uint32_t a;
    asm("{ .reg .u64 t; cvta.to.shared.u64 t, %1; cvt.u32.u64 %0, t; }" : "=r"(a) : "l"(p));
    return a;
}
__device__ __forceinline__ void cp16(uint32_t dst, const void* src) {
    asm volatile("cp.async.cg.shared.global [%0], [%1], 16;" :: "r"(dst), "l"(src));
}
__device__ __forceinline__ void cp_commit() { asm volatile("cp.async.commit_group;" ::: "memory"); }
__device__ __forceinline__ void cp_wait0()  { asm volatile("cp.async.wait_group 0;" ::: "memory"); }
__device__ __forceinline__ void cp_wait1()  { asm volatile("cp.async.wait_group 1;" ::: "memory"); }
__device__ __forceinline__ void ldm_x4(uint32_t* r, uint32_t addr) {
    asm volatile("ldmatrix.sync.aligned.m8n8.x4.shared.b16 {%0,%1,%2,%3}, [%4];"
        : "=r"(r[0]), "=r"(r[1]), "=r"(r[2]), "=r"(r[3]) : "r"(addr));
}
__device__ __forceinline__ void mma_f16(float* d, const uint32_t* a, const uint32_t* b) {
    asm volatile("mma.sync.aligned.m16n8k16.row.col.f32.f16.f16.f32 "
        "{%0,%1,%2,%3}, {%4,%5,%6,%7}, {%8,%9}, {%0,%1,%2,%3};"
        : "+f"(d[0]), "+f"(d[1]), "+f"(d[2]), "+f"(d[3])
        : "r"(a[0]), "r"(a[1]), "r"(a[2]), "r"(a[3]), "r"(b[0]), "r"(b[1]));
}
__device__ __forceinline__ uint32_t pack_h2(__half a, __half b) {
    return (uint32_t)__half_as_ushort(a) | ((uint32_t)__half_as_ushort(b) << 16);
}

// Swizzled smem byte offset for (row, 16B-chunk) within a 128x32x16bit tile (64B rows)
__device__ __forceinline__ uint32_t sw_off(int r, int c) {
    return (uint32_t)(r * 64 + ((c ^ ((r >> 1) & 3)) << 4));
}

// ---------------------------------------------------------------------------
// Tile loader: one 128x32 fp16 A tile + one B tile into {sb+0, sb+8K}
// ---------------------------------------------------------------------------
__device__ __forceinline__ void issue_tile(
    uint32_t sb,
    const __half* __restrict__ A, int sA,
    const __half* __restrict__ B, int sB,
    int tid)
{
    const int r  = tid >> 1;
    const int c0 = (tid & 1) * 2;
    const uint32_t o1 = sw_off(r, c0);
    const uint32_t o2 = sw_off(r, c0 + 1);
    const size_t ra = (size_t)r * sA + c0 * 8;
    const size_t rb = (size_t)r * sB + c0 * 8;
    cp16(sb +     0 + o1, A + ra);      cp16(sb +     0 + o2, A + ra + 8);
    cp16(sb +  8192 + o1, B + rb);      cp16(sb +  8192 + o2, B + rb + 8);
}

// One pipeline step = two independent 32-K tiles (64 K total)
__device__ __forceinline__ void issue_step(
    uint32_t sb,
    const __half* __restrict__ A, int sA,
    const __half* __restrict__ B, int sB,
    int tid)
{
    issue_tile(sb,          A,          sA, B,          sB, tid);
    issue_tile(sb + 16384u, A + KCHUNK, sA, B + KCHUNK, sB, tid);
}

// ---------------------------------------------------------------------------
// fp16 1-term mainloop (ALL GEMMs): acc += A(fp16) * B(fp16).
// 3-stage ring of 64-K steps; ONE sync + ONE wait per 64 K (halved overhead).
// nsteps = K / 64 (all K extents here are multiples of 64).
// ---------------------------------------------------------------------------
__device__ __forceinline__ void run_gemm_t2(
    const __half* __restrict__ A, int sA,
    const __half* __restrict__ B, int sB,
    int nsteps, uint32_t sbase, float acc[4][4][4])
{
    const int tid  = threadIdx.x;
    const int wid  = tid >> 5;
    const int lane = tid & 31;
    const int wm = (wid >> 2) * 64;
    const int wn = (wid & 3) * 32;
    const int lr = lane & 15;
    const int lc = lane >> 4;

    issue_step(sbase, A, sA, B, sB, tid);
    cp_commit();
    if (nsteps > 1)
        issue_step(sbase + T2_STAGE_BYTES, A + 2 * KCHUNK, sA, B + 2 * KCHUNK, sB, tid);
    cp_commit();

    uint32_t st = sbase;
    int stage = 0;
    for (int s = 0; s < nsteps; s++) {
        if (s + 1 < nsteps) cp_wait1(); else cp_wait0();
        __syncthreads();
        if (s + 2 < nsteps) {
            const size_t ko = (size_t)(s + 2) * (2 * KCHUNK);
            int s2 = stage + 2; if (s2 >= T2_NSTAGE) s2 -= T2_NSTAGE;
            issue_step(sbase + (uint32_t)s2 * T2_STAGE_BYTES,
                       A + ko, sA, B + ko, sB, tid);
        }
        cp_commit();

        #pragma unroll
        for (int h = 0; h < 2; h++) {
            const uint32_t base = st + (uint32_t)h * 16384u;
            #pragma unroll
            for (int ks = 0; ks < 2; ks++) {
                const int kch = 2 * ks + lc;
                uint32_t bB[4][2];
                #pragma unroll
                for (int j2 = 0; j2 < 2; j2++) {
                    int r = wn + j2 * 16 + lr;
                    uint32_t t4[4];
                    ldm_x4(t4, base + 8192 + sw_off(r, kch));
                    bB[2*j2][0] = t4[0]; bB[2*j2+1][0] = t4[1];
                    bB[2*j2][1] = t4[2]; bB[2*j2+1][1] = t4[3];
                }
                #pragma unroll
                for (int i = 0; i < 4; i++) {
                    uint32_t aA[4];
                    int r = wm + i * 16 + lr;
                    ldm_x4(aA, base + sw_off(r, kch));
                    #pragma unroll
                    for (int j = 0; j < 4; j++)
                        mma_f16(acc[i][j], aA, bB[j]);
                }
            }
        }
        stage++; if (stage >= T2_NSTAGE) stage = 0;
        st = sbase + (uint32_t)stage * T2_STAGE_BYTES;
    }
}

// Accumulator element coords: tile (i,j), reg r ->
//   row = wm + i*16 + (lane>>2) + 8*(r>>1),  col = wn + j*8 + 2*(lane&3) + (r&1)

// ---------------------------------------------------------------------------
// x, W -> single fp16.
// ---------------------------------------------------------------------------
__global__ __launch_bounds__(256) void conv_kernel(
    const float* __restrict__ x, const float* __restrict__ Wq,
    const float* __restrict__ Wk, const float* __restrict__ Wv)
{
    int idx = blockIdx.x * 256 + threadIdx.x;
    g_x16[idx] = __float2half_rn(x[idx]);
    if (idx < DIMN * DIMN) {
        g_w16[idx]                   = __float2half_rn(Wq[idx]);
        g_w16[DIMN * DIMN + idx]     = __float2half_rn(Wk[idx]);
        g_w16[2 * DIMN * DIMN + idx] = __float2half_rn(Wv[idx]);
    }
}

// ---------------------------------------------------------------------------
// Q/K projection (fp16 1-term). grid (4, 64, 2).
// ---------------------------------------------------------------------------
__global__ __launch_bounds__(256, 2) void qkv_mma_kernel(
    const float* __restrict__ bq, const float* __restrict__ bk)
{
    extern __shared__ __align__(16) char dsm[];
    uint32_t sbase = smem_u32(dsm);

    const int z = blockIdx.z;
    const int row0 = blockIdx.y * 128;
    const int col0 = blockIdx.x * 128;
    const float* bias = (z == 0) ? bq : bk;

    float acc[4][4][4];
    #pragma unroll
    for (int i = 0; i < 4; i++)
        #pragma unroll
        for (int j = 0; j < 4; j++)
            #pragma unroll
            for (int r = 0; r < 4; r++) acc[i][j][r] = 0.f;

    run_gemm_t2(g_x16 + (size_t)row0 * DIMN, DIMN,
                g_w16 + (size_t)z * DIMN * DIMN + (size_t)col0 * DIMN, DIMN,
                DIMN / 64, sbase, acc);

    const int tid = threadIdx.x, wid = tid >> 5, lane = tid & 31;
    const int wm = (wid >> 2) * 64, wn = (wid & 3) * 32;

    __half* dst = (z == 0) ? g_q16 : g_k16;
    const float sc = (z == 0) ? 1.f : SCALE;
    #pragma unroll
    for (int i = 0; i < 4; i++)
        #pragma unroll
        for (int j = 0; j < 4; j++)
            #pragma unroll
            for (int rh = 0; rh < 2; rh++) {
                int rr = row0 + wm + i * 16 + (lane >> 2) + 8 * rh;
                int cc = col0 + wn + j * 8 + 2 * (lane & 3);
                float v0 = (acc[i][j][2 * rh + 0] + bias[cc + 0]) * sc;
                float v1 = (acc[i][j][2 * rh + 1] + bias[cc + 1]) * sc;
                *(uint32_t*)(dst + (size_t)rr * DIMN + cc) =
                    pack_h2(__float2half_rn(v0), __float2half_rn(v1));
            }
}

// ---------------------------------------------------------------------------
// Scores + V projection, one grid (4352 blocks, 1D):
//   blocks [0, 256): V projection tiles (fp16 1-term -> V^T fp16 via half smem)
//   blocks [256, 4352): causal score tiles -> RAW fp16 scores into g_aw
// ---------------------------------------------------------------------------
__global__ __launch_bounds__(256, 2) void scores_mma_kernel(
    float* __restrict__ attn, const float* __restrict__ bv)
{
    extern __shared__ __align__(16) char dsm[];
    uint32_t sbase = smem_u32(dsm);
    const int tid = threadIdx.x, wid = tid >> 5, lane = tid & 31;
    const int wm = (wid >> 2) * 64, wn = (wid & 3) * 32;

    if (blockIdx.x < 256) {
        // ---- V projection tile ----
        const int vt = blockIdx.x;
        const int col0 = (vt & 3) * 128;   // headdim tile
        const int row0 = (vt >> 2) * 128;  // seq tile

        float acc[4][4][4];
        #pragma unroll
        for (int i = 0; i < 4; i++)
            #pragma unroll
            for (int j = 0; j < 4; j++)
                #pragma unroll
                for (int r = 0; r < 4; r++) acc[i][j][r] = 0.f;

        run_gemm_t2(g_x16 + (size_t)row0 * DIMN, DIMN,
                    g_w16 + (size_t)2 * DIMN * DIMN + (size_t)col0 * DIMN, DIMN,
                    DIMN / 64, sbase, acc);

        // transpose through HALF smem (values are fp16-rounded anyway), pitch 136
        __syncthreads();
        __half* tsm = (__half*)dsm;            // [128][136] halves = 34.8 KB
        #pragma unroll
        for (int i = 0; i < 4; i++)
            #pragma unroll
            for (int j = 0; j < 4; j++)
                #pragma unroll
                for (int r = 0; r < 4; r++) {
                    int lrr = wm + i * 16 + (lane >> 2) + 8 * (r >> 1);
                    int lcc = wn + j * 8 + 2 * (lane & 3) + (r & 1);
                    tsm[lcc * 136 + lrr] = __float2half_rn(acc[i][j][r] + bv[col0 + lcc]);
                }
        __syncthreads();
        #pragma unroll
        for (int it = 0; it < 8; it++) {
            int idx = it * 256 + tid;
            int vr = idx >> 4;
            int c8 = (idx & 15) * 8;
            uint32_t hw[4];
            #pragma unroll
            for (int m = 0; m < 4; m++)
                hw[m] = *(const uint32_t*)(tsm + vr * 136 + c8 + 2 * m);
            *(uint4*)(g_vth + (size_t)(col0 + vr) * SQ + row0 + c8) =
                make_uint4(hw[0], hw[1], hw[2], hw[3]);
        }
        return;
    }

    // ---- score tile ----
    const int t = blockIdx.x - 256;
    const int bi = t >> 6, bj = t & 63;
    const int row0 = bi * 128, col0 = bj * 128;

    if (bj > bi) {
        // final attn weights here are exactly 0 (fp32 output only)
        float4 z = make_float4(0.f, 0.f, 0.f, 0.f);
        #pragma unroll 4
        for (int idx = tid; idx < 128 * 32; idx += 256) {
            int r = idx >> 5, c = (idx & 31) << 2;
            *(float4*)(attn + (size_t)(row0 + r) * SQ + col0 + c) = z;
        }
        return;
    }

    float acc[4][4][4];
    #pragma unroll
    for (int i = 0; i < 4; i++)
        #pragma unroll
        for (int j = 0; j < 4; j++)
            #pragma unroll
            for (int r = 0; r < 4; r++) acc[i][j][r] = 0.f;

    run_gemm_t2(g_q16 + (size_t)row0 * DIMN, DIMN,
                g_k16 + (size_t)col0 * DIMN, DIMN,
                DIMN / 64, sbase, acc);

    const bool diag = (bi == bj);
    #pragma unroll
    for (int i = 0; i < 4; i++)
        #pragma unroll
        for (int j = 0; j < 4; j++)
            #pragma unroll
            for (int rh = 0; rh < 2; rh++) {
                int rr = row0 + wm + i * 16 + (lane >> 2) + 8 * rh;
                int cc = col0 + wn + j * 8 + 2 * (lane & 3);
                float v0 = acc[i][j][2 * rh + 0];
                float v1 = acc[i][j][2 * rh + 1];
                if (diag) {
                    // masked entries stay 0 in g_aw: softmax never rewrites
                    // j > rr, and AV then accumulates exact 0 for them.
                    if (cc + 0 > rr) v0 = 0.f;
                    if (cc + 1 > rr) v1 = 0.f;
                }
                *(uint32_t*)(g_aw + (size_t)rr * SQ + cc) =
                    pack_h2(__float2half_rn(v0), __float2half_rn(v1));
            }
}

// ---------------------------------------------------------------------------
// Causal softmax: read raw fp16 scores from g_aw, write fp32 weights to attn
// and fp16 weights back to g_aw. Heavy rows first.
// ---------------------------------------------------------------------------
__global__ __launch_bounds__(256) void softmax_kernel(float* __restrict__ attn)
{
    __shared__ __align__(16) float buf[SQ];
    __shared__ float red[32];
    __shared__ float s_bcast;

    const int i = SQ - 1 - blockIdx.x;     // longest rows scheduled first
    const int L = i + 1;
    const int L4 = L >> 2;
    const int tail = L & 3;
    float* row = attn + (size_t)i * SQ;
    __half* aw = g_aw + (size_t)i * SQ;
    const int tid = threadIdx.x;

    float mx = -3.4e38f;
    for (int j4 = tid; j4 < L4; j4 += 256) {
        uint2 p = ((const uint2*)aw)[j4];
        __half2 h01 = *(__half2*)&p.x;
        __half2 h23 = *(__half2*)&p.y;
        float4 s;
        s.x = __low2float(h01);  s.y = __high2float(h01);
        s.z = __low2float(h23);  s.w = __high2float(h23);
        ((float4*)buf)[j4] = s;
        mx = fmaxf(fmaxf(mx, fmaxf(s.x, s.y)), fmaxf(s.z, s.w));
    }
    if (tid < tail) {
        int j = L4 * 4 + tid;
        float s = __half2float(aw[j]);
        buf[j] = s;
        mx = fmaxf(mx, s);
    }
    #pragma unroll
    for (int o = 16; o; o >>= 1) mx = fmaxf(mx, __shfl_xor_sync(0xffffffffu, mx, o));
    if ((tid & 31) == 0) red[tid >> 5] = mx;
    __syncthreads();
    if (tid < 32) {
        float v = (tid < 8) ? red[tid] : -3.4e38f;
        #pragma unroll
        for (int o = 4; o; o >>= 1) v = fmaxf(v, __shfl_xor_sync(0xffffffffu, v, o));
        if (tid == 0) s_bcast = v;
    }
    __syncthreads();
    mx = s_bcast;

    float sum = 0.f;
    for (int j4 = tid; j4 < L4; j4 += 256) {
        float4 e = ((const float4*)buf)[j4];
        e.x = __expf(e.x - mx); e.y = __expf(e.y - mx);
        e.z = __expf(e.z - mx); e.w = __expf(e.w - mx);
        ((float4*)buf)[j4] = e;
        sum += (e.x + e.y) + (e.z + e.w);
    }
    if (tid < tail) {
        int j = L4 * 4 + tid;
        float e = __expf(buf[j] - mx);
        buf[j] = e;
        sum += e;
    }
    #pragma unroll
    for (int o = 16; o; o >>= 1) sum += __shfl_xor_sync(0xffffffffu, sum, o);
    __syncthreads();
    if ((tid & 31) == 0) red[tid >> 5] = sum;
    __syncthreads();
    if (tid < 32) {
        float v = (tid < 8) ? red[tid] : 0.f;
        #pragma unroll
        for (int o = 4; o; o >>= 1) v += __shfl_xor_sync(0xffffffffu, v, o);
        if (tid == 0) s_bcast = 1.f / v;
    }
    __syncthreads();
    const float inv = s_bcast;

    for (int j4 = tid; j4 < L4; j4 += 256) {
        float4 w = ((const float4*)buf)[j4];
        w.x *= inv; w.y *= inv; w.z *= inv; w.w *= inv;
        ((float4*)row)[j4] = w;
        uint2 hw;
        hw.x = pack_h2(__float2half_rn(w.x), __float2half_rn(w.y));
        hw.y = pack_h2(__float2half_rn(w.z), __float2half_rn(w.w));
        *(uint2*)(aw + j4 * 4) = hw;
    }
    if (tid < tail) {
        int j = L4 * 4 + tid;
        float w = buf[j] * inv;
        row[j] = w;
        aw[j] = __float2half_rn(w);
    }
}

// ---------------------------------------------------------------------------
// output = attn(fp16) @ V(fp16), split-K seg width 2048. grid (4, 64, 4).
// Heavy row-tiles first; bm<16 tiles write out directly (single segment).
// ---------------------------------------------------------------------------
__global__ __launch_bounds__(256, 2) void av_mma_kernel(float* __restrict__ out)
{
    const int bn = blockIdx.x;
    const int bm = 63 - blockIdx.y;           // heaviest first
    const int seg = blockIdx.z;
    const int nseg = (bm + 16) >> 4;           // ceil((bm+1)/16)
    if (seg >= nseg) return;

    const int row0 = bm * 128, col0 = bn * 128;
    const int k0 = seg * KSEG;
    const int ktot = (bm + 1) * 128;
    const int kend = (k0 + KSEG < ktot) ? (k0 + KSEG) : ktot;
    const int nsteps = (kend - k0) / 64;       // always even # of 32-K chunks

    extern __shared__ __align__(16) char dsm[];
    uint32_t sbase = smem_u32(dsm);

    float acc[4][4][4];
    #pragma unroll
    for (int i = 0; i < 4; i++)
        #pragma unroll
        for (int j = 0; j < 4; j++)
            #pragma unroll
            for (int r = 0; r < 4; r++) acc[i][j][r] = 0.f;

    run_gemm_t2(g_aw  + (size_t)row0 * SQ + k0, SQ,
                g_vth + (size_t)col0 * SQ + k0, SQ,
                nsteps, sbase, acc);

    const int tid = threadIdx.x, wid = tid >> 5, lane = tid & 31;
    const int wm = (wid >> 2) * 64, wn = (wid & 3) * 32;

    if (nseg == 1) {
        #pragma unroll
        for (int i = 0; i < 4; i++)
            #pragma unroll
            for (int j = 0; j < 4; j++)
                #pragma unroll
                for (int rh = 0; rh < 2; rh++) {
                    int rr = row0 + wm + i * 16 + (lane >> 2) + 8 * rh;
                    int cc = col0 + wn + j * 8 + 2 * (lane & 3);
                    float2 v;
                    v.x = acc[i][j][2 * rh + 0];
                    v.y = acc[i][j][2 * rh + 1];
                    *(float2*)(out + (size_t)rr * DIMN + cc) = v;
                }
    } else {
        float* slot = g_part + ((size_t)((bm * 4 + bn) * 4 + seg)) * 16384;
        #pragma unroll
        for (int i = 0; i < 4; i++)
            #pragma unroll
            for (int j = 0; j < 4; j++)
                #pragma unroll
                for (int rh = 0; rh < 2; rh++) {
                    int lrr = wm + i * 16 + (lane >> 2) + 8 * rh;
                    int lcc = wn + j * 8 + 2 * (lane & 3);
                    float2 v;
                    v.x = acc[i][j][2 * rh + 0];
                    v.y = acc[i][j][2 * rh + 1];
                    *(float2*)(slot + lrr * 128 + lcc) = v;
                }
    }
}

// ---------------------------------------------------------------------------
// Deterministic split-K reduction for tiles with bm >= 16. grid (4, 48).
// ---------------------------------------------------------------------------
__global__ __launch_bounds__(256) void av_reduce_kernel(float* __restrict__ out)
{
    const int bn = blockIdx.x, bm = 16 + blockIdx.y;
    const int nseg = (bm + 16) >> 4;
    const int row0 = bm * 128, col0 = bn * 128;
    const float* base = g_part + ((size_t)((bm * 4 + bn) * 4)) * 16384;

    for (int idx = threadIdx.x; idx < 4096; idx += 256) {
        float4 s = *(const float4*)(base + idx * 4);
        for (int sg = 1; sg < nseg; sg++) {
            float4 p = *(const float4*)(base + (size_t)sg * 16384 + idx * 4);
            s.x += p.x; s.y += p.y; s.z += p.z; s.w += p.w;
        }
        int lr = idx >> 5, lc = (idx & 31) << 2;
        *(float4*)(out + (size_t)(row0 + lr) * DIMN + col0 + lc) = s;
    }
}

// ---------------------------------------------------------------------------
extern "C" void kernel_launch(void* const* d_in, const int* in_sizes, int n_in,
                              void* d_out, int out_size)
{
    const float* x  = (const float*)d_in[0];
    const float* Wq = (const float*)d_in[1];
    const float* bq = (const float*)d_in[2];
    const float* Wk = (const float*)d_in[3];
    const float* bk = (const float*)d_in[4];
    const float* Wv = (const float*)d_in[5];
    const float* bv = (const float*)d_in[6];

    float* out  = (float*)d_out;                 // [S, D]
    float* attn = out + (size_t)SQ * DIMN;       // [S, S]

    const int T2_SMEM_BYTES = T2_NSTAGE * (int)T2_STAGE_BYTES;    // 96 KB
    cudaFuncSetAttribute(qkv_mma_kernel,    cudaFuncAttributeMaxDynamicSharedMemorySize, T2_SMEM_BYTES);
    cudaFuncSetAttribute(scores_mma_kernel, cudaFuncAttributeMaxDynamicSharedMemorySize, T2_SMEM_BYTES);
    cudaFuncSetAttribute(av_mma_kernel,     cudaFuncAttributeMaxDynamicSharedMemorySize, T2_SMEM_BYTES);

    conv_kernel<<<(SQ * DIMN) / 256, 256>>>(x, Wq, Wk, Wv);

    dim3 g_qkv(DIMN / 128, SQ / 128, 2);                 // q, k only
    qkv_mma_kernel<<<g_qkv, 256, T2_SMEM_BYTES>>>(bq, bk);

    scores_mma_kernel<<<256 + 64 * 64, 256, T2_SMEM_BYTES>>>(attn, bv);

    softmax_kernel<<<SQ, 256>>>(attn);

    dim3 g_av(4, 64, 4);
    av_mma_kernel<<<g_av, 256, T2_SMEM_BYTES>>>(out);

    dim3 g_red(4, 48);
    av_reduce_kernel<<<g_red, 256>>>(out);
}

// round 16
// speedup vs baseline: 1.0624x; 1.0624x over previous
#include <cuda_runtime.h>
#include <cuda_fp16.h>
#include <cstdint>

#define SQ 8192
#define DIMN 512
#define SCALE 0.04419417382415922f  // 1/sqrt(512)
#define KCHUNK 32                   // k per pipeline stage
#define T1_STAGE_BYTES 16384u       // 1-term fp16: A 8KB + B 8KB
#define T1_NSTAGE 4
#define KSEG 2048                   // AV split-K segment width

// fp16 operands (zero-initialized device globals)
__device__ __half g_x16[SQ * DIMN];                            // x single fp16
__device__ __half g_w16[3 * DIMN * DIMN];                      // Wq|Wk|Wv single fp16
__device__ __half g_q16[SQ * DIMN];
__device__ __half g_k16[SQ * DIMN];                            // pre-scaled by SCALE
__device__ __half g_vth[DIMN * SQ];                            // V^T: [512, 8192]
__device__ __half g_aw[(size_t)SQ * SQ];                       // raw scores -> weights
// split-K partials for AV: 256 tiles x 4 segs x 128x128 fp32 = 64 MB
__device__ float g_part[(size_t)256 * 4 * 16384];

// ---------------------------------------------------------------------------
// PTX helpers (base-ISA only: ldmatrix / mma.sync / cp.async)
// ---------------------------------------------------------------------------
__device__ __forceinline__ uint32_t smem_u32(const void* p) {
    uint32_t a;
    asm("{ .reg .u64 t; cvta.to.shared.u64 t, %1; cvt.u32.u64 %0, t; }" : "=r"(a) : "l"(p));
    return a;
}
__device__ __forceinline__ void cp16(uint32_t dst, const void* src) {
    asm volatile("cp.async.cg.shared.global [%0], [%1], 16;" :: "r"(dst), "l"(src));
}
__device__ __forceinline__ void cp_commit() { asm volatile("cp.async.commit_group;" ::: "memory"); }
__device__ __forceinline__ void cp_wait2()  { asm volatile("cp.async.wait_group 2;" ::: "memory"); }
__device__ __forceinline__ void ldm_x4(uint32_t* r, uint32_t addr) {
    asm volatile("ldmatrix.sync.aligned.m8n8.x4.shared.b16 {%0,%1,%2,%3}, [%4];"
        : "=r"(r[0]), "=r"(r[1]), "=r"(r[2]), "=r"(r[3]) : "r"(addr));
}
__device__ __forceinline__ void mma_f16(float* d, const uint32_t* a, const uint32_t* b) {
    asm volatile("mma.sync.aligned.m16n8k16.row.col.f32.f16.f16.f32 "
        "{%0,%1,%2,%3}, {%4,%5,%6,%7}, {%8,%9}, {%0,%1,%2,%3};"
        : "+f"(d[0]), "+f"(d[1]), "+f"(d[2]), "+f"(d[3])
        : "r"(a[0]), "r"(a[1]), "r"(a[2]), "r"(a[3]), "r"(b[0]), "r"(b[1]));
}
__device__ __forceinline__ uint32_t pack_h2(__half a, __half b) {
    return (uint32_t)__half_as_ushort(a) | ((uint32_t)__half_as_ushort(b) << 16);
}
// streaming (evict-first) stores for write-once fp32 output
__device__ __forceinline__ void st_cs_f4(float* p, float4 v) {
    asm volatile("st.global.cs.v4.f32 [%0], {%1,%2,%3,%4};"
                 :: "l"(p), "f"(v.x), "f"(v.y), "f"(v.z), "f"(v.w) : "memory");
}
__device__ __forceinline__ void st_cs_f2(float* p, float2 v) {
    asm volatile("st.global.cs.v2.f32 [%0], {%1,%2};"
                 :: "l"(p), "f"(v.x), "f"(v.y) : "memory");
}

// Swizzled smem byte offset for (row, 16B-chunk) within a 128x32x16bit tile (64B rows)
__device__ __forceinline__ uint32_t sw_off(int r, int c) {
    return (uint32_t)(r * 64 + ((c ^ ((r >> 1) & 3)) << 4));
}

// ---------------------------------------------------------------------------
__device__ __forceinline__ void issue_chunk_t1(
    uint32_t sb,
    const __half* __restrict__ A, int sA,
    const __half* __restrict__ B, int sB,
    int tid)
{
    const int r  = tid >> 1;
    const int c0 = (tid & 1) * 2;
    const uint32_t o1 = sw_off(r, c0);
    const uint32_t o2 = sw_off(r, c0 + 1);
    const size_t ra = (size_t)r * sA + c0 * 8;
    const size_t rb = (size_t)r * sB + c0 * 8;
    cp16(sb +     0 + o1, A + ra);      cp16(sb +     0 + o2, A + ra + 8);
    cp16(sb +  8192 + o1, B + rb);      cp16(sb +  8192 + o2, B + rb + 8);
}

// ---------------------------------------------------------------------------
// fp16 1-term mainloop (ALL GEMMs): acc += A(fp16) * B(fp16). 4-stage.
// (R14-proven structure — do not modify.)
// ---------------------------------------------------------------------------
__device__ __forceinline__ void run_gemm_t1(
    const __half* __restrict__ A, int sA,
    const __half* __restrict__ B, int sB,
    int nchunks, uint32_t sbase, float acc[4][4][4])
{
    const int tid  = threadIdx.x;
    const int wid  = tid >> 5;
    const int lane = tid & 31;
    const int wm = (wid >> 2) * 64;
    const int wn = (wid & 3) * 32;
    const int lr = lane & 15;
    const int lc = lane >> 4;

    #pragma unroll
    for (int p = 0; p < 3; p++) {
        if (p < nchunks)
            issue_chunk_t1(sbase + (uint32_t)p * T1_STAGE_BYTES,
                           A + (size_t)p * KCHUNK, sA,
                           B + (size_t)p * KCHUNK, sB, tid);
        cp_commit();
    }

    uint32_t st = sbase;
    int stage = 0;
    for (int c = 0; c < nchunks; c++) {
        cp_wait2();
        __syncthreads();
        if (c + 3 < nchunks) {
            const size_t ko = (size_t)(c + 3) * KCHUNK;
            int s3 = stage + 3; if (s3 >= T1_NSTAGE) s3 -= T1_NSTAGE;
            issue_chunk_t1(sbase + (uint32_t)s3 * T1_STAGE_BYTES,
                           A + ko, sA, B + ko, sB, tid);
        }
        cp_commit();

        #pragma unroll
        for (int ks = 0; ks < 2; ks++) {
            const int kch = 2 * ks + lc;
            uint32_t bB[4][2];
            #pragma unroll
            for (int j2 = 0; j2 < 2; j2++) {
                int r = wn + j2 * 16 + lr;
                uint32_t t4[4];
                ldm_x4(t4, st + 8192 + sw_off(r, kch));
                bB[2*j2][0] = t4[0]; bB[2*j2+1][0] = t4[1];
                bB[2*j2][1] = t4[2]; bB[2*j2+1][1] = t4[3];
            }
            #pragma unroll
            for (int i = 0; i < 4; i++) {
                uint32_t aA[4];
                int r = wm + i * 16 + lr;
                ldm_x4(aA, st + sw_off(r, kch));
                #pragma unroll
                for (int j = 0; j < 4; j++)
                    mma_f16(acc[i][j], aA, bB[j]);
            }
        }
        stage++; if (stage >= T1_NSTAGE) stage = 0;
        st = sbase + (uint32_t)stage * T1_STAGE_BYTES;
    }
}

// Accumulator element coords: tile (i,j), reg r ->
//   row = wm + i*16 + (lane>>2) + 8*(r>>1),  col = wn + j*8 + 2*(lane&3) + (r&1)

// ---------------------------------------------------------------------------
// x, W -> single fp16.
// ---------------------------------------------------------------------------
__global__ __launch_bounds__(256) void conv_kernel(
    const float* __restrict__ x, const float* __restrict__ Wq,
    const float* __restrict__ Wk, const float* __restrict__ Wv)
{
    int idx = blockIdx.x * 256 + threadIdx.x;
    g_x16[idx] = __float2half_rn(x[idx]);
    if (idx < DIMN * DIMN) {
        g_w16[idx]                   = __float2half_rn(Wq[idx]);
        g_w16[DIMN * DIMN + idx]     = __float2half_rn(Wk[idx]);
        g_w16[2 * DIMN * DIMN + idx] = __float2half_rn(Wv[idx]);
    }
}

// ---------------------------------------------------------------------------
// Q/K projection (fp16 1-term). grid (4, 64, 2).
// ---------------------------------------------------------------------------
__global__ __launch_bounds__(256, 2) void qkv_mma_kernel(
    const float* __restrict__ bq, const float* __restrict__ bk)
{
    extern __shared__ __align__(16) char dsm[];
    uint32_t sbase = smem_u32(dsm);

    const int z = blockIdx.z;
    const int row0 = blockIdx.y * 128;
    const int col0 = blockIdx.x * 128;
    const float* bias = (z == 0) ? bq : bk;

    float acc[4][4][4];
    #pragma unroll
    for (int i = 0; i < 4; i++)
        #pragma unroll
        for (int j = 0; j < 4; j++)
            #pragma unroll
            for (int r = 0; r < 4; r++) acc[i][j][r] = 0.f;

    run_gemm_t1(g_x16 + (size_t)row0 * DIMN, DIMN,
                g_w16 + (size_t)z * DIMN * DIMN + (size_t)col0 * DIMN, DIMN,
                DIMN / KCHUNK, sbase, acc);

    const int tid = threadIdx.x, wid = tid >> 5, lane = tid & 31;
    const int wm = (wid >> 2) * 64, wn = (wid & 3) * 32;

    __half* dst = (z == 0) ? g_q16 : g_k16;
    const float sc = (z == 0) ? 1.f : SCALE;
    #pragma unroll
    for (int i = 0; i < 4; i++)
        #pragma unroll
        for (int j = 0; j < 4; j++)
            #pragma unroll
            for (int rh = 0; rh < 2; rh++) {
                int rr = row0 + wm + i * 16 + (lane >> 2) + 8 * rh;
                int cc = col0 + wn + j * 8 + 2 * (lane & 3);
                float v0 = (acc[i][j][2 * rh + 0] + bias[cc + 0]) * sc;
                float v1 = (acc[i][j][2 * rh + 1] + bias[cc + 1]) * sc;
                *(uint32_t*)(dst + (size_t)rr * DIMN + cc) =
                    pack_h2(__float2half_rn(v0), __float2half_rn(v1));
            }
}

// ---------------------------------------------------------------------------
// Scores + V projection, one grid (4352 blocks, 1D):
//   blocks [0, 256): V projection tiles (fp16 1-term -> V^T fp16 via half smem)
//   blocks [256, 4352): causal score tiles -> RAW fp16 scores into g_aw
// ---------------------------------------------------------------------------
__global__ __launch_bounds__(256, 2) void scores_mma_kernel(
    float* __restrict__ attn, const float* __restrict__ bv)
{
    extern __shared__ __align__(16) char dsm[];
    uint32_t sbase = smem_u32(dsm);
    const int tid = threadIdx.x, wid = tid >> 5, lane = tid & 31;
    const int wm = (wid >> 2) * 64, wn = (wid & 3) * 32;

    if (blockIdx.x < 256) {
        // ---- V projection tile ----
        const int vt = blockIdx.x;
        const int col0 = (vt & 3) * 128;   // headdim tile
        const int row0 = (vt >> 2) * 128;  // seq tile

        float acc[4][4][4];
        #pragma unroll
        for (int i = 0; i < 4; i++)
            #pragma unroll
            for (int j = 0; j < 4; j++)
                #pragma unroll
                for (int r = 0; r < 4; r++) acc[i][j][r] = 0.f;

        run_gemm_t1(g_x16 + (size_t)row0 * DIMN, DIMN,
                    g_w16 + (size_t)2 * DIMN * DIMN + (size_t)col0 * DIMN, DIMN,
                    DIMN / KCHUNK, sbase, acc);

        // transpose through HALF smem (values are fp16-rounded anyway), pitch 136
        __syncthreads();
        __half* tsm = (__half*)dsm;            // [128][136] halves = 34.8 KB
        #pragma unroll
        for (int i = 0; i < 4; i++)
            #pragma unroll
            for (int j = 0; j < 4; j++)
                #pragma unroll
                for (int r = 0; r < 4; r++) {
                    int lrr = wm + i * 16 + (lane >> 2) + 8 * (r >> 1);
                    int lcc = wn + j * 8 + 2 * (lane & 3) + (r & 1);
                    tsm[lcc * 136 + lrr] = __float2half_rn(acc[i][j][r] + bv[col0 + lcc]);
                }
        __syncthreads();
        #pragma unroll
        for (int it = 0; it < 8; it++) {
            int idx = it * 256 + tid;
            int vr = idx >> 4;
            int c8 = (idx & 15) * 8;
            uint32_t hw[4];
            #pragma unroll
            for (int m = 0; m < 4; m++)
                hw[m] = *(const uint32_t*)(tsm + vr * 136 + c8 + 2 * m);
            *(uint4*)(g_vth + (size_t)(col0 + vr) * SQ + row0 + c8) =
                make_uint4(hw[0], hw[1], hw[2], hw[3]);
        }
        return;
    }

    // ---- score tile ----
    const int t = blockIdx.x - 256;
    const int bi = t >> 6, bj = t & 63;
    const int row0 = bi * 128, col0 = bj * 128;

    if (bj > bi) {
        // final attn weights here are exactly 0 (fp32 output only, never re-read)
        float4 z = make_float4(0.f, 0.f, 0.f, 0.f);
        #pragma unroll 4
        for (int idx = tid; idx < 128 * 32; idx += 256) {
            int r = idx >> 5, c = (idx & 31) << 2;
            st_cs_f4(attn + (size_t)(row0 + r) * SQ + col0 + c, z);
        }
        return;
    }

    float acc[4][4][4];
    #pragma unroll
    for (int i = 0; i < 4; i++)
        #pragma unroll
        for (int j = 0; j < 4; j++)
            #pragma unroll
            for (int r = 0; r < 4; r++) acc[i][j][r] = 0.f;

    run_gemm_t1(g_q16 + (size_t)row0 * DIMN, DIMN,
                g_k16 + (size_t)col0 * DIMN, DIMN,
                DIMN / KCHUNK, sbase, acc);

    const bool diag = (bi == bj);
    #pragma unroll
    for (int i = 0; i < 4; i++)
        #pragma unroll
        for (int j = 0; j < 4; j++)
            #pragma unroll
            for (int rh = 0; rh < 2; rh++) {
                int rr = row0 + wm + i * 16 + (lane >> 2) + 8 * rh;
                int cc = col0 + wn + j * 8 + 2 * (lane & 3);
                float v0 = acc[i][j][2 * rh + 0];
                float v1 = acc[i][j][2 * rh + 1];
                if (diag) {
                    // masked entries stay 0 in g_aw: softmax never rewrites
                    // j > rr, and AV then accumulates exact 0 for them.
                    if (cc + 0 > rr) v0 = 0.f;
                    if (cc + 1 > rr) v1 = 0.f;
                }
                *(uint32_t*)(g_aw + (size_t)rr * SQ + cc) =
                    pack_h2(__float2half_rn(v0), __float2half_rn(v1));
            }
}

// ---------------------------------------------------------------------------
// Causal softmax: read raw fp16 scores from g_aw, write fp32 weights to attn
// (streaming stores — pure output) and fp16 weights back to g_aw. Heavy first.
// ---------------------------------------------------------------------------
__global__ __launch_bounds__(256) void softmax_kernel(float* __restrict__ attn)
{
    __shared__ __align__(16) float buf[SQ];
    __shared__ float red[32];
    __shared__ float s_bcast;

    const int i = SQ - 1 - blockIdx.x;     // longest rows scheduled first
    const int L = i + 1;
    const int L4 = L >> 2;
    const int tail = L & 3;
    float* row = attn + (size_t)i * SQ;
    __half* aw = g_aw + (size_t)i * SQ;
    const int tid = threadIdx.x;

    float mx = -3.4e38f;
    for (int j4 = tid; j4 < L4; j4 += 256) {
        uint2 p = ((const uint2*)aw)[j4];
        __half2 h01 = *(__half2*)&p.x;
        __half2 h23 = *(__half2*)&p.y;
        float4 s;
        s.x = __low2float(h01);  s.y = __high2float(h01);
        s.z = __low2float(h23);  s.w = __high2float(h23);
        ((float4*)buf)[j4] = s;
        mx = fmaxf(fmaxf(mx, fmaxf(s.x, s.y)), fmaxf(s.z, s.w));
    }
    if (tid < tail) {
        int j = L4 * 4 + tid;
        float s = __half2float(aw[j]);
        buf[j] = s;
        mx = fmaxf(mx, s);
    }
    #pragma unroll
    for (int o = 16; o; o >>= 1) mx = fmaxf(mx, __shfl_xor_sync(0xffffffffu, mx, o));
    if ((tid & 31) == 0) red[tid >> 5] = mx;
    __syncthreads();
    if (tid < 32) {
        float v = (tid < 8) ? red[tid] : -3.4e38f;
        #pragma unroll
        for (int o = 4; o; o >>= 1) v = fmaxf(v, __shfl_xor_sync(0xffffffffu, v, o));
        if (tid == 0) s_bcast = v;
    }
    __syncthreads();
    mx = s_bcast;

    float sum = 0.f;
    for (int j4 = tid; j4 < L4; j4 += 256) {
        float4 e = ((const float4*)buf)[j4];
        e.x = __expf(e.x - mx); e.y = __expf(e.y - mx);
        e.z = __expf(e.z - mx); e.w = __expf(e.w - mx);
        ((float4*)buf)[j4] = e;
        sum += (e.x + e.y) + (e.z + e.w);
    }
    if (tid < tail) {
        int j = L4 * 4 + tid;
        float e = __expf(buf[j] - mx);
        buf[j] = e;
        sum += e;
    }
    #pragma unroll
    for (int o = 16; o; o >>= 1) sum += __shfl_xor_sync(0xffffffffu, sum, o);
    __syncthreads();
    if ((tid & 31) == 0) red[tid >> 5] = sum;
    __syncthreads();
    if (tid < 32) {
        float v = (tid < 8) ? red[tid] : 0.f;
        #pragma unroll
        for (int o = 4; o; o >>= 1) v += __shfl_xor_sync(0xffffffffu, v, o);
        if (tid == 0) s_bcast = 1.f / v;
    }
    __syncthreads();
    const float inv = s_bcast;

    for (int j4 = tid; j4 < L4; j4 += 256) {
        float4 w = ((const float4*)buf)[j4];
        w.x *= inv; w.y *= inv; w.z *= inv; w.w *= inv;
        st_cs_f4(row + j4 * 4, w);
        uint2 hw;
        hw.x = pack_h2(__float2half_rn(w.x), __float2half_rn(w.y));
        hw.y = pack_h2(__float2half_rn(w.z), __float2half_rn(w.w));
        *(uint2*)(aw + j4 * 4) = hw;
    }
    if (tid < tail) {
        int j = L4 * 4 + tid;
        float w = buf[j] * inv;
        asm volatile("st.global.cs.f32 [%0], %1;" :: "l"(row + j), "f"(w) : "memory");
        aw[j] = __float2half_rn(w);
    }
}

// ---------------------------------------------------------------------------
// output = attn(fp16) @ V(fp16), split-K seg width 2048. grid (4, 64, 4).
// Heavy row-tiles first; bm<16 tiles write out directly (single segment).
// ---------------------------------------------------------------------------
__global__ __launch_bounds__(256, 2) void av_mma_kernel(float* __restrict__ out)
{
    const int bn = blockIdx.x;
    const int bm = 63 - blockIdx.y;           // heaviest first
    const int seg = blockIdx.z;
    const int nseg = (bm + 16) >> 4;           // ceil((bm+1)/16)
    if (seg >= nseg) return;

    const int row0 = bm * 128, col0 = bn * 128;
    const int k0 = seg * KSEG;
    const int ktot = (bm + 1) * 128;
    const int kend = (k0 + KSEG < ktot) ? (k0 + KSEG) : ktot;
    const int nchunks = (kend - k0) / KCHUNK;

    extern __shared__ __align__(16) char dsm[];
    uint32_t sbase = smem_u32(dsm);

    float acc[4][4][4];
    #pragma unroll
    for (int i = 0; i < 4; i++)
        #pragma unroll
        for (int j = 0; j < 4; j++)
            #pragma unroll
            for (int r = 0; r < 4; r++) acc[i][j][r] = 0.f;

    run_gemm_t1(g_aw  + (size_t)row0 * SQ + k0, SQ,
                g_vth + (size_t)col0 * SQ + k0, SQ,
                nchunks, sbase, acc);

    const int tid = threadIdx.x, wid = tid >> 5, lane = tid & 31;
    const int wm = (wid >> 2) * 64, wn = (wid & 3) * 32;

    if (nseg == 1) {
        #pragma unroll
        for (int i = 0; i < 4; i++)
            #pragma unroll
            for (int j = 0; j < 4; j++)
                #pragma unroll
                for (int rh = 0; rh < 2; rh++) {
                    int rr = row0 + wm + i * 16 + (lane >> 2) + 8 * rh;
                    int cc = col0 + wn + j * 8 + 2 * (lane & 3);
                    float2 v;
                    v.x = acc[i][j][2 * rh + 0];
                    v.y = acc[i][j][2 * rh + 1];
                    st_cs_f2(out + (size_t)rr * DIMN + cc, v);
                }
    } else {
        float* slot = g_part + ((size_t)((bm * 4 + bn) * 4 + seg)) * 16384;
        #pragma unroll
        for (int i = 0; i < 4; i++)
            #pragma unroll
            for (int j = 0; j < 4; j++)
                #pragma unroll
                for (int rh = 0; rh < 2; rh++) {
                    int lrr = wm + i * 16 + (lane >> 2) + 8 * rh;
                    int lcc = wn + j * 8 + 2 * (lane & 3);
                    float2 v;
                    v.x = acc[i][j][2 * rh + 0];
                    v.y = acc[i][j][2 * rh + 1];
                    *(float2*)(slot + lrr * 128 + lcc) = v;
                }
    }
}

// ---------------------------------------------------------------------------
// Deterministic split-K reduction for tiles with bm >= 16. grid (4, 48).
// ---------------------------------------------------------------------------
__global__ __launch_bounds__(256) void av_reduce_kernel(float* __restrict__ out)
{
    const int bn = blockIdx.x, bm = 16 + blockIdx.y;
    const int nseg = (bm + 16) >> 4;
    const int row0 = bm * 128, col0 = bn * 128;
    const float* base = g_part + ((size_t)((bm * 4 + bn) * 4)) * 16384;

    for (int idx = threadIdx.x; idx < 4096; idx += 256) {
        float4 s = *(const float4*)(base + idx * 4);
        for (int sg = 1; sg < nseg; sg++) {
            float4 p = *(const float4*)(base + (size_t)sg * 16384 + idx * 4);
            s.x += p.x; s.y += p.y; s.z += p.z; s.w += p.w;
        }
        int lr = idx >> 5, lc = (idx & 31) << 2;
        st_cs_f4(out + (size_t)(row0 + lr) * DIMN + col0 + lc, s);
    }
}

// ---------------------------------------------------------------------------
extern "C" void kernel_launch(void* const* d_in, const int* in_sizes, int n_in,
                              void* d_out, int out_size)
{
    const float* x  = (const float*)d_in[0];
    const float* Wq = (const float*)d_in[1];
    const float* bq = (const float*)d_in[2];
    const float* Wk = (const float*)d_in[3];
    const float* bk = (const float*)d_in[4];
    const float* Wv = (const float*)d_in[5];
    const float* bv = (const float*)d_in[6];

    float* out  = (float*)d_out;                 // [S, D]
    float* attn = out + (size_t)SQ * DIMN;       // [S, S]

    const int T1_SMEM_BYTES = T1_NSTAGE * (int)T1_STAGE_BYTES;    // 64 KB
    cudaFuncSetAttribute(qkv_mma_kernel,    cudaFuncAttributeMaxDynamicSharedMemorySize, T1_SMEM_BYTES);
    cudaFuncSetAttribute(scores_mma_kernel, cudaFuncAttributeMaxDynamicSharedMemorySize, T1_SMEM_BYTES);
    cudaFuncSetAttribute(av_mma_kernel,     cudaFuncAttributeMaxDynamicSharedMemorySize, T1_SMEM_BYTES);

    conv_kernel<<<(SQ * DIMN) / 256, 256>>>(x, Wq, Wk, Wv);

    dim3 g_qkv(DIMN / 128, SQ / 128, 2);                 // q, k only
    qkv_mma_kernel<<<g_qkv, 256, T1_SMEM_BYTES>>>(bq, bk);

    scores_mma_kernel<<<256 + 64 * 64, 256, T1_SMEM_BYTES>>>(attn, bv);

    softmax_kernel<<<SQ, 256>>>(attn);

    dim3 g_av(4, 64, 4);
    av_mma_kernel<<<g_av, 256, T1_SMEM_BYTES>>>(out);

    dim3 g_red(4, 48);
    av_reduce_kernel<<<g_red, 256>>>(out);
}